// round 14
// baseline (speedup 1.0000x reference)
#include <cuda_runtime.h>
#include <cuda_bf16.h>
#include <math.h>
#include <stdint.h>

// Problem constants
constexpr int B  = 4;
constexpr int S  = 1024;
constexpr int H  = 16;
constexpr int M  = B * S;          // 4096
constexpr int NN = H * 64;         // 1024
constexpr int KK = 1024;

// ===========================================================================
// Global scratch (device globals: allocation-free). bf16 hi/lo dataflow.
// ===========================================================================
__device__ __nv_bfloat16 g_xh[3][(size_t)M * KK];   // converted inputs q,k,v
__device__ __nv_bfloat16 g_xl[3][(size_t)M * KK];
__device__ __nv_bfloat16 g_wth[4][(size_t)NN * KK]; // transposed weights [n][k]
__device__ __nv_bfloat16 g_wtl[4][(size_t)NN * KK];
__device__ __nv_bfloat16 g_oh[3][(size_t)M * NN];   // qw,kw,vw (proj outputs)
__device__ __nv_bfloat16 g_ol[3][(size_t)M * NN];
__device__ __nv_bfloat16 g_ath[(size_t)M * NN];     // attention output
__device__ __nv_bfloat16 g_atl[(size_t)M * NN];

// ===========================================================================
// Helpers
// ===========================================================================
__device__ __forceinline__ uint32_t smem_u32(const void* p) {
    uint32_t a;
    asm("{ .reg .u64 t; cvta.to.shared.u64 t, %1; cvt.u32.u64 %0, t; }"
        : "=r"(a) : "l"(p));
    return a;
}
__device__ __forceinline__ uint64_t gaddr(const void* p) {
    uint64_t r;
    asm("cvta.to.global.u64 %0, %1;" : "=l"(r) : "l"(p));
    return r;
}
__device__ __forceinline__ uint32_t pk2(float a, float b) {
    __nv_bfloat162 t;
    t.x = __float2bfloat16(a);
    t.y = __float2bfloat16(b);
    return *(uint32_t*)&t;
}
__device__ __forceinline__ float bres(float x) {   // residual after bf16 hi
    __nv_bfloat16 h = __float2bfloat16(x);
    return x - __bfloat162float(h);
}
__device__ __forceinline__ void bar_sync(int id, int cnt) {
    asm volatile("bar.sync %0, %1;" :: "r"(id), "r"(cnt) : "memory");
}
__device__ __forceinline__ void bar_arrive(int id, int cnt) {
    asm volatile("bar.arrive %0, %1;" :: "r"(id), "r"(cnt) : "memory");
}

// 64B-row swizzle (GEMM tiles: 32 bf16 per row), chunk 0..3
__device__ __forceinline__ int sw_off(int row, int chunk) {
    return row * 64 + ((chunk ^ ((row >> 1) & 3) ^ ((row >> 3) & 3)) << 4);
}
// 128B-row swizzle (flash tiles: 64 bf16 per row), chunk 0..7
__device__ __forceinline__ int fsw(int row, int chunk) {
    return row * 128 + ((chunk ^ (row & 7)) << 4);
}

#define LDMX4(r, addr) \
    asm volatile("ldmatrix.sync.aligned.m8n8.x4.shared.b16 {%0,%1,%2,%3}, [%4];" \
        : "=r"((r)[0]), "=r"((r)[1]), "=r"((r)[2]), "=r"((r)[3]) : "r"(addr))
#define LDMX4T(r, addr) \
    asm volatile("ldmatrix.sync.aligned.m8n8.x4.trans.shared.b16 {%0,%1,%2,%3}, [%4];" \
        : "=r"((r)[0]), "=r"((r)[1]), "=r"((r)[2]), "=r"((r)[3]) : "r"(addr))
#define MMA_BF16(d, a, bb) \
    asm volatile("mma.sync.aligned.m16n8k16.row.col.f32.bf16.bf16.f32 " \
        "{%0,%1,%2,%3}, {%4,%5,%6,%7}, {%8,%9}, {%0,%1,%2,%3};" \
        : "+f"((d)[0]), "+f"((d)[1]), "+f"((d)[2]), "+f"((d)[3]) \
        : "r"((a)[0]), "r"((a)[1]), "r"((a)[2]), "r"((a)[3]), \
          "r"((bb)[0]), "r"((bb)[1]))
#define CP16(dst, src) \
    asm volatile("cp.async.cg.shared.global [%0], [%1], 16;" \
        :: "r"((uint32_t)(dst)), "l"((uint64_t)(src)))
#define CP_COMMIT() asm volatile("cp.async.commit_group;" ::: "memory")
#define CP_WAIT0()  asm volatile("cp.async.wait_group 0;" ::: "memory")
#define CP_WAIT1()  asm volatile("cp.async.wait_group 1;" ::: "memory")
#define CP_WAIT2()  asm volatile("cp.async.wait_group 2;" ::: "memory")

// ===========================================================================
// Merged conversion kernel (z 0..2: inputs, z 3..6: transposed weights)
// ===========================================================================
__global__ void conv_all(const float* __restrict__ q,
                         const float* __restrict__ k,
                         const float* __restrict__ v,
                         const float* __restrict__ Wq,
                         const float* __restrict__ Wk,
                         const float* __restrict__ Wv,
                         const float* __restrict__ Wo)
{
    const int z = blockIdx.z;
    if (z < 3) {
        const float* src = (z == 0) ? q : (z == 1) ? k : v;
        uint2* dh = (uint2*)g_xh[z];
        uint2* dl = (uint2*)g_xl[z];
        const int n4 = M * KK / 4;
        for (int i = blockIdx.x * blockDim.x + threadIdx.x; i < n4;
             i += gridDim.x * blockDim.x) {
            float4 x = ((const float4*)src)[i];
            uint2 hi, lo;
            hi.x = pk2(x.x, x.y);             hi.y = pk2(x.z, x.w);
            lo.x = pk2(bres(x.x), bres(x.y)); lo.y = pk2(bres(x.z), bres(x.w));
            dh[i] = hi;
            dl[i] = lo;
        }
    } else {
        __shared__ float t[32][33];
        const int zw = z - 3;
        const float* W = (zw == 0) ? Wq : (zw == 1) ? Wk : (zw == 2) ? Wv : Wo;
        __nv_bfloat16* th = g_wth[zw];
        __nv_bfloat16* tl = g_wtl[zw];
        const int nb = (blockIdx.x & 31) * 32;
        const int kb = (blockIdx.x >> 5) * 32;
        const int tx = threadIdx.x & 31, ty = threadIdx.x >> 5;  // ty 0..7
#pragma unroll
        for (int j = 0; j < 4; ++j)
            t[ty + 8 * j][tx] = W[(size_t)(kb + ty + 8 * j) * NN + nb + tx];
        __syncthreads();
#pragma unroll
        for (int j = 0; j < 4; ++j) {
            const float val = t[tx][ty + 8 * j];
            const size_t o = (size_t)(nb + ty + 8 * j) * KK + kb + tx;
            __nv_bfloat16 h = __float2bfloat16(val);
            th[o] = h;
            tl[o] = __float2bfloat16(val - __bfloat162float(h));
        }
    }
}

// ===========================================================================
// Warp-specialized bf16 split GEMM: 128(M) x 64(N), BK=32, 320 threads.
// Warps 0..7 = consumers (4m x 2n, warp 32x32), warps 8..9 = producers.
// 3 stages x 24KB dynamic smem. Named-barrier handoff:
//   FULL(s)=id 1+s  (producer arrives, consumers sync; 64+256=320)
//   EMPTY(s)=id 4+s (consumers arrive, producers sync; 256+64=320)
// Producer at iter u: sync EMPTY(u%3) [u>=3], issue stage u, commit,
//   wait_group 2 -> stage u-2 complete -> fence -> arrive FULL((u-2)%3).
// Consumer at iter t: sync FULL(t%3), MMA, arrive EMPTY(t%3).
// ===========================================================================
constexpr int BM = 128, BN = 64, BK = 32;
constexpr int STGB = 24576;
constexpr int AHI = 0, ALO = 8192, BHI = 16384, BLO = 20480;
constexpr int NT = KK / BK;
constexpr int NTHR = 320;
constexpr int GEMM_DSMEM  = 3 * STGB;            // 73728
constexpr int FLASH_DSMEM = 16384 + 3 * 32768;   // 114688

__device__ __forceinline__ void prod_issue(uint64_t Ah, uint64_t Al,
                                           uint64_t Bh, uint64_t Bl,
                                           int k0, int tp, uint32_t stg)
{
#pragma unroll
    for (int j = 0; j < 24; ++j) {
        const int cidx = j * 64 + tp;
        if (cidx < 1024) {                      // A region (compile-time per j)
            const int half = cidx >> 9;         // 0 hi, 1 lo
            const int idx  = cidx & 511;
            const int r = idx >> 2, c = idx & 3;
            const uint64_t src = (half ? Al : Ah)
                + (uint64_t)r * (KK * 2) + (uint64_t)(k0 + c * 8) * 2;
            CP16(stg + (half ? ALO : AHI) + sw_off(r, c), src);
        } else {                                // B region
            const int idx  = cidx - 1024;       // 0..511
            const int half = idx >> 8;
            const int i2   = idx & 255;
            const int r = i2 >> 2, c = i2 & 3;
            const uint64_t src = (half ? Bl : Bh)
                + (uint64_t)r * (KK * 2) + (uint64_t)(k0 + c * 8) * 2;
            CP16(stg + (half ? BLO : BHI) + sw_off(r, c), src);
        }
    }
}

__device__ __forceinline__ void gemm_core_ws(uint64_t Ah, uint64_t Al,
                                             uint64_t Bh, uint64_t Bl,
                                             int m0, int n0, int lane,
                                             float acc[2][4][4])
{
    extern __shared__ __align__(128) char dynsm[];
    const uint32_t sbase = smem_u32(dynsm);
    const int tid = threadIdx.x;

    if (tid >= 256) {
        // -------- producer warps --------
        const int tp = tid - 256;
        for (int t = 0; t < NT; ++t) {
            if (t >= 3) bar_sync(4 + t % 3, NTHR);
            prod_issue(Ah, Al, Bh, Bl, t * BK, tp, sbase + (t % 3) * STGB);
            CP_COMMIT();
            if (t >= 2) {
                CP_WAIT2();
                __threadfence_block();
                bar_arrive(1 + (t - 2) % 3, NTHR);
            }
        }
        CP_WAIT1();
        __threadfence_block();
        bar_arrive(1 + (NT - 2) % 3, NTHR);
        CP_WAIT0();
        __threadfence_block();
        bar_arrive(1 + (NT - 1) % 3, NTHR);
        return;
    }

    // -------- consumer warps --------
#pragma unroll
    for (int mt = 0; mt < 2; ++mt)
#pragma unroll
        for (int nt = 0; nt < 4; ++nt)
#pragma unroll
            for (int i = 0; i < 4; ++i) acc[mt][nt][i] = 0.f;

    for (int t = 0; t < NT; ++t) {
        bar_sync(1 + t % 3, NTHR);
        const uint32_t sA = sbase + (t % 3) * STGB;
        const uint32_t sB = sA + BHI;
#pragma unroll
        for (int ks = 0; ks < 2; ++ks) {
            uint32_t ah[2][4], al[2][4], bh2[4][2], bl2[4][2];
#pragma unroll
            for (int mt = 0; mt < 2; ++mt) {
                const int row = m0 + mt * 16 + (lane & 15);
                const int ch  = ks * 2 + (lane >> 4);
                const uint32_t ad = sA + sw_off(row, ch);
                LDMX4(ah[mt], ad);
                LDMX4(al[mt], ad + ALO);
            }
#pragma unroll
            for (int np = 0; np < 2; ++np) {
                const int nr = n0 + np * 16 + ((lane >> 4) << 3) + (lane & 7);
                const int ch = ks * 2 + ((lane >> 3) & 1);
                const uint32_t ad = sB + sw_off(nr, ch);
                uint32_t th[4], tl[4];
                LDMX4(th, ad);
                LDMX4(tl, ad + (BLO - BHI));
                bh2[np * 2][0] = th[0]; bh2[np * 2][1] = th[1];
                bh2[np * 2 + 1][0] = th[2]; bh2[np * 2 + 1][1] = th[3];
                bl2[np * 2][0] = tl[0]; bl2[np * 2][1] = tl[1];
                bl2[np * 2 + 1][0] = tl[2]; bl2[np * 2 + 1][1] = tl[3];
            }
#pragma unroll
            for (int mt = 0; mt < 2; ++mt)
#pragma unroll
                for (int nt = 0; nt < 4; ++nt) {
                    MMA_BF16(acc[mt][nt], ah[mt], bh2[nt]);
                    MMA_BF16(acc[mt][nt], ah[mt], bl2[nt]);
                    MMA_BF16(acc[mt][nt], al[mt], bh2[nt]);
                }
        }
        bar_arrive(4 + t % 3, NTHR);
    }
}

// QKV projection: writes bf16 hi/lo outputs for flash
__global__ __launch_bounds__(NTHR, 2)
void qkv_v5(const float* __restrict__ bq, const float* __restrict__ bk,
            const float* __restrict__ bv)
{
    const int z = blockIdx.z;
    const float* bias = (z == 0) ? bq : (z == 1) ? bk : bv;
    const int tid = threadIdx.x, lane = tid & 31, w = tid >> 5;
    const int m0 = (w >> 1) * 32, n0 = (w & 1) * 32;
    const int bm = blockIdx.y * BM, bn = blockIdx.x * BN;

    const uint64_t Ah = gaddr(g_xh[z])  + (uint64_t)bm * KK * 2;
    const uint64_t Al = gaddr(g_xl[z])  + (uint64_t)bm * KK * 2;
    const uint64_t Bh = gaddr(g_wth[z]) + (uint64_t)bn * KK * 2;
    const uint64_t Bl = gaddr(g_wtl[z]) + (uint64_t)bn * KK * 2;

    float acc[2][4][4];
    gemm_core_ws(Ah, Al, Bh, Bl, m0, n0, lane, acc);
    if (tid >= 256) return;

    __nv_bfloat16* Yh = g_oh[z];
    __nv_bfloat16* Yl = g_ol[z];
#pragma unroll
    for (int nt = 0; nt < 4; ++nt) {
        const int gc = bn + n0 + nt * 8 + (lane & 3) * 2;
        const float b0 = bias[gc], b1 = bias[gc + 1];
#pragma unroll
        for (int mt = 0; mt < 2; ++mt) {
            const int gr = bm + m0 + mt * 16 + (lane >> 2);
            const float y0 = acc[mt][nt][0] + b0;
            const float y1 = acc[mt][nt][1] + b1;
            const float y2 = acc[mt][nt][2] + b0;
            const float y3 = acc[mt][nt][3] + b1;
            *(uint32_t*)&Yh[(size_t)gr * NN + gc]       = pk2(y0, y1);
            *(uint32_t*)&Yl[(size_t)gr * NN + gc]       = pk2(bres(y0), bres(y1));
            *(uint32_t*)&Yh[(size_t)(gr + 8) * NN + gc] = pk2(y2, y3);
            *(uint32_t*)&Yl[(size_t)(gr + 8) * NN + gc] = pk2(bres(y2), bres(y3));
        }
    }
}

// Output projection: A = attention output (bf16 hi/lo), fp32 out, q_mask
__global__ __launch_bounds__(NTHR, 2)
void out_v5(const float* __restrict__ bo, float* __restrict__ out,
            const int* __restrict__ qmask)
{
    const int tid = threadIdx.x, lane = tid & 31, w = tid >> 5;
    const int m0 = (w >> 1) * 32, n0 = (w & 1) * 32;
    const int bm = blockIdx.y * BM, bn = blockIdx.x * BN;

    const uint64_t Ah = gaddr(g_ath)    + (uint64_t)bm * KK * 2;
    const uint64_t Al = gaddr(g_atl)    + (uint64_t)bm * KK * 2;
    const uint64_t Bh = gaddr(g_wth[3]) + (uint64_t)bn * KK * 2;
    const uint64_t Bl = gaddr(g_wtl[3]) + (uint64_t)bn * KK * 2;

    float acc[2][4][4];
    gemm_core_ws(Ah, Al, Bh, Bl, m0, n0, lane, acc);
    if (tid >= 256) return;

#pragma unroll
    for (int nt = 0; nt < 4; ++nt) {
        const int gc = bn + n0 + nt * 8 + (lane & 3) * 2;
        const float b0 = bo[gc], b1 = bo[gc + 1];
#pragma unroll
        for (int mt = 0; mt < 2; ++mt) {
            const int gr = bm + m0 + mt * 16 + (lane >> 2);
            const float s0 = (float)qmask[gr];
            const float s1 = (float)qmask[gr + 8];
            float2 v0, v1;
            v0.x = (acc[mt][nt][0] + b0) * s0;
            v0.y = (acc[mt][nt][1] + b1) * s0;
            v1.x = (acc[mt][nt][2] + b0) * s1;
            v1.y = (acc[mt][nt][3] + b1) * s1;
            *(float2*)(out + (size_t)gr * NN + gc)       = v0;
            *(float2*)(out + (size_t)(gr + 8) * NN + gc) = v1;
        }
    }
}

// ===========================================================================
// Flash attention v4 (unchanged from R13): 128 q-rows/CTA, 8 warps,
// 3 KV stages, cp.async prefetch depth 1, one __syncthreads per tile.
// ===========================================================================
constexpr int FQB = 0, FSTG0 = 16384, FSTGB = 32768;
constexpr int FKL_O = 8192, FVH_O = 16384, FVL_O = 24576;  // within stage

__device__ __forceinline__ void flash_issue(uint64_t Kh, uint64_t Kl,
                                            uint64_t Vh, uint64_t Vl,
                                            int b, int t, int hc, int tid,
                                            uint32_t stg)
{
#pragma unroll
    for (int i = 0; i < 2; ++i) {
        const int id = tid + i * 256;
        const int r = id >> 3, c = id & 7;
        const uint64_t off = ((uint64_t)(b * S + t * 64 + r) * NN + hc + c * 8) * 2;
        const int sw = fsw(r, c);
        CP16(stg + sw,         Kh + off);
        CP16(stg + FKL_O + sw, Kl + off);
        CP16(stg + FVH_O + sw, Vh + off);
        CP16(stg + FVL_O + sw, Vl + off);
    }
}

__global__ __launch_bounds__(256, 2)
void flash_v4(const int* __restrict__ v_mask)
{
    extern __shared__ __align__(128) char dynsm[];
    const uint32_t sb = smem_u32(dynsm);
    const int tid  = threadIdx.x;
    const int lane = tid & 31;
    const int w    = tid >> 5;         // 0..7
    const int m0   = w * 16;           // 0..112
    const int bh   = blockIdx.y;
    const int b    = bh >> 4;
    const int h    = bh & 15;
    const int q0   = blockIdx.x * 128;
    const int hc   = h * 64;

    const uint64_t Qh = gaddr(g_oh[0]);
    const uint64_t Ql = gaddr(g_ol[0]);
    const uint64_t Kh = gaddr(g_oh[1]);
    const uint64_t Kl = gaddr(g_ol[1]);
    const uint64_t Vh = gaddr(g_oh[2]);
    const uint64_t Vl = gaddr(g_ol[2]);

    // ---- Q phase 1: hi into QB, read frags ----
    uint32_t qh[4][4], ql[4][4];
    {
#pragma unroll
        for (int i = 0; i < 4; ++i) {
            const int id = tid + i * 256;
            const int r = id >> 3, c = id & 7;
            CP16(sb + FQB + fsw(r, c),
                 Qh + ((uint64_t)(b * S + q0 + r) * NN + hc + c * 8) * 2);
        }
        CP_COMMIT(); CP_WAIT0();
    }
    __syncthreads();
#pragma unroll
    for (int ks = 0; ks < 4; ++ks) {
        const int row = m0 + (lane & 15);
        const int ch  = ks * 2 + (lane >> 4);
        LDMX4(qh[ks], sb + FQB + fsw(row, ch));
    }
    __syncthreads();
    // ---- Q phase 2: lo into QB (reuse), read frags ----
    {
#pragma unroll
        for (int i = 0; i < 4; ++i) {
            const int id = tid + i * 256;
            const int r = id >> 3, c = id & 7;
            CP16(sb + FQB + fsw(r, c),
                 Ql + ((uint64_t)(b * S + q0 + r) * NN + hc + c * 8) * 2);
        }
        CP_COMMIT(); CP_WAIT0();
    }
    __syncthreads();
#pragma unroll
    for (int ks = 0; ks < 4; ++ks) {
        const int row = m0 + (lane & 15);
        const int ch  = ks * 2 + (lane >> 4);
        LDMX4(ql[ks], sb + FQB + fsw(row, ch));
    }

    const float NEGINF = __int_as_float(0xff800000);
    float m_[2] = {NEGINF, NEGINF};
    float l_[2] = {0.f, 0.f};
    float o[8][4];
#pragma unroll
    for (int nt = 0; nt < 8; ++nt)
#pragma unroll
        for (int i = 0; i < 4; ++i) o[nt][i] = 0.f;

    const int diag2 = 2 * blockIdx.x + 1;   // last causal-needed tile

    // prefetch KV tile 0 -> stage 0
    flash_issue(Kh, Kl, Vh, Vl, b, 0, hc, tid, sb + FSTG0);
    CP_COMMIT();

    int s_cur = 0, s_nxt = 1;
    for (int t = 0; t < 16; ++t) {
        if (t + 1 < 16) {
            flash_issue(Kh, Kl, Vh, Vl, b, t + 1, hc, tid,
                        sb + FSTG0 + s_nxt * FSTGB);
            CP_COMMIT();
            CP_WAIT1();
        } else {
            CP_WAIT0();
        }
        __syncthreads();   // single barrier: tile t visible; 3-stage rotation
                           // keeps writes (t+1) clear of slowest readers (t-1)

        const uint32_t sK = sb + FSTG0 + s_cur * FSTGB;
        const uint32_t sV = sK + FVH_O;

        // ---- S = Q K^T (split-bf16, 3 passes) ----
        float sc[8][4];
#pragma unroll
        for (int nt = 0; nt < 8; ++nt)
#pragma unroll
            for (int i = 0; i < 4; ++i) sc[nt][i] = 0.f;
#pragma unroll
        for (int ks = 0; ks < 4; ++ks) {
            uint32_t kbh[8][2], kbl[8][2];
#pragma unroll
            for (int np = 0; np < 4; ++np) {
                const int nr = np * 16 + ((lane >> 4) << 3) + (lane & 7);
                const int ch = ks * 2 + ((lane >> 3) & 1);
                const uint32_t ad = sK + fsw(nr, ch);
                uint32_t th[4], tl[4];
                LDMX4(th, ad);
                LDMX4(tl, ad + FKL_O);
                kbh[np * 2][0] = th[0]; kbh[np * 2][1] = th[1];
                kbh[np * 2 + 1][0] = th[2]; kbh[np * 2 + 1][1] = th[3];
                kbl[np * 2][0] = tl[0]; kbl[np * 2][1] = tl[1];
                kbl[np * 2 + 1][0] = tl[2]; kbl[np * 2 + 1][1] = tl[3];
            }
#pragma unroll
            for (int nt = 0; nt < 8; ++nt) {
                MMA_BF16(sc[nt], qh[ks], kbh[nt]);
                MMA_BF16(sc[nt], qh[ks], kbl[nt]);
                MMA_BF16(sc[nt], ql[ks], kbh[nt]);
            }
        }

        // ---- mask + online softmax (v_mask from global/L1) ----
        const int r0g = q0 + m0 + (lane >> 2);
        const int r1g = r0g + 8;
        const int vmb = b * S + t * 64;
        float tmax0 = NEGINF, tmax1 = NEGINF;
#pragma unroll
        for (int nt = 0; nt < 8; ++nt) {
            const int c0  = nt * 8 + (lane & 3) * 2;
            const int cg0 = t * 64 + c0;
            const float p0 = (1.0f - (float)__ldg(&v_mask[vmb + c0]))     * 1e12f;
            const float p1 = (1.0f - (float)__ldg(&v_mask[vmb + c0 + 1])) * 1e12f;
            float s0 = sc[nt][0] * 0.125f - p0; if (cg0     > r0g) s0 -= 1e12f;
            float s1 = sc[nt][1] * 0.125f - p1; if (cg0 + 1 > r0g) s1 -= 1e12f;
            float s2 = sc[nt][2] * 0.125f - p0; if (cg0     > r1g) s2 -= 1e12f;
            float s3 = sc[nt][3] * 0.125f - p1; if (cg0 + 1 > r1g) s3 -= 1e12f;
            sc[nt][0] = s0; sc[nt][1] = s1; sc[nt][2] = s2; sc[nt][3] = s3;
            tmax0 = fmaxf(tmax0, fmaxf(s0, s1));
            tmax1 = fmaxf(tmax1, fmaxf(s2, s3));
        }
        tmax0 = fmaxf(tmax0, __shfl_xor_sync(0xffffffffu, tmax0, 1));
        tmax0 = fmaxf(tmax0, __shfl_xor_sync(0xffffffffu, tmax0, 2));
        tmax1 = fmaxf(tmax1, __shfl_xor_sync(0xffffffffu, tmax1, 1));
        tmax1 = fmaxf(tmax1, __shfl_xor_sync(0xffffffffu, tmax1, 2));
        const float mn0 = fmaxf(m_[0], tmax0);
        const float mn1 = fmaxf(m_[1], tmax1);
        const float al0 = __expf(m_[0] - mn0);
        const float al1 = __expf(m_[1] - mn1);
        float rs0 = 0.f, rs1 = 0.f;
#pragma unroll
        for (int nt = 0; nt < 8; ++nt) {
            sc[nt][0] = __expf(sc[nt][0] - mn0); rs0 += sc[nt][0];
            sc[nt][1] = __expf(sc[nt][1] - mn0); rs0 += sc[nt][1];
            sc[nt][2] = __expf(sc[nt][2] - mn1); rs1 += sc[nt][2];
            sc[nt][3] = __expf(sc[nt][3] - mn1); rs1 += sc[nt][3];
        }
        rs0 += __shfl_xor_sync(0xffffffffu, rs0, 1);
        rs0 += __shfl_xor_sync(0xffffffffu, rs0, 2);
        rs1 += __shfl_xor_sync(0xffffffffu, rs1, 1);
        rs1 += __shfl_xor_sync(0xffffffffu, rs1, 2);
        l_[0] = l_[0] * al0 + rs0;
        l_[1] = l_[1] * al1 + rs1;
        m_[0] = mn0;
        m_[1] = mn1;
#pragma unroll
        for (int nt = 0; nt < 8; ++nt) {
            o[nt][0] *= al0; o[nt][1] *= al0;
            o[nt][2] *= al1; o[nt][3] *= al1;
        }

        // ---- O += P V (P repacked in registers; V via ldmatrix.trans) ----
#pragma unroll
        for (int kt = 0; kt < 4; ++kt) {
            uint32_t pah[4], pal[4];
            pah[0] = pk2(sc[2 * kt][0],     sc[2 * kt][1]);
            pah[1] = pk2(sc[2 * kt][2],     sc[2 * kt][3]);
            pah[2] = pk2(sc[2 * kt + 1][0], sc[2 * kt + 1][1]);
            pah[3] = pk2(sc[2 * kt + 1][2], sc[2 * kt + 1][3]);
            pal[0] = pk2(bres(sc[2 * kt][0]),     bres(sc[2 * kt][1]));
            pal[1] = pk2(bres(sc[2 * kt][2]),     bres(sc[2 * kt][3]));
            pal[2] = pk2(bres(sc[2 * kt + 1][0]), bres(sc[2 * kt + 1][1]));
            pal[3] = pk2(bres(sc[2 * kt + 1][2]), bres(sc[2 * kt + 1][3]));
#pragma unroll
            for (int np = 0; np < 4; ++np) {
                const int key = kt * 16 + (lane & 7) + ((lane >> 3) & 1) * 8;
                const int ch  = np * 2 + (lane >> 4);
                const uint32_t ad = sV + fsw(key, ch);
                uint32_t vh4[4], vl4[4];
                LDMX4T(vh4, ad);
                LDMX4T(vl4, ad + (FVL_O - FVH_O));
                uint32_t vb0h[2] = {vh4[0], vh4[1]}, vb1h[2] = {vh4[2], vh4[3]};
                uint32_t vb0l[2] = {vl4[0], vl4[1]}, vb1l[2] = {vl4[2], vl4[3]};
                MMA_BF16(o[np * 2],     pah, vb0h);
                MMA_BF16(o[np * 2],     pah, vb0l);
                MMA_BF16(o[np * 2],     pal, vb0h);
                MMA_BF16(o[np * 2 + 1], pah, vb1h);
                MMA_BF16(o[np * 2 + 1], pah, vb1l);
                MMA_BF16(o[np * 2 + 1], pal, vb1h);
            }
        }

        // Past diagonal: continue only while some row is still fully masked
        if (t >= diag2) {
            int pred = (mn0 <= -1e11f) | (mn1 <= -1e11f);
            if (!__syncthreads_or(pred)) break;
        }
        s_cur = (s_cur == 2) ? 0 : s_cur + 1;
        s_nxt = (s_nxt == 2) ? 0 : s_nxt + 1;
    }

    // ---- normalize + store as bf16 hi/lo for the output projection ----
    const float inv0 = 1.0f / l_[0];
    const float inv1 = 1.0f / l_[1];
    const int gr0 = b * S + q0 + m0 + (lane >> 2);
#pragma unroll
    for (int nt = 0; nt < 8; ++nt) {
        const int col = hc + nt * 8 + (lane & 3) * 2;
        const float a0 = o[nt][0] * inv0, a1 = o[nt][1] * inv0;
        const float a2 = o[nt][2] * inv1, a3 = o[nt][3] * inv1;
        *(uint32_t*)&g_ath[(size_t)gr0 * NN + col]       = pk2(a0, a1);
        *(uint32_t*)&g_atl[(size_t)gr0 * NN + col]       = pk2(bres(a0), bres(a1));
        *(uint32_t*)&g_ath[(size_t)(gr0 + 8) * NN + col] = pk2(a2, a3);
        *(uint32_t*)&g_atl[(size_t)(gr0 + 8) * NN + col] = pk2(bres(a2), bres(a3));
    }
}

// ---------------------------------------------------------------------------
extern "C" void kernel_launch(void* const* d_in, const int* in_sizes, int n_in,
                              void* d_out, int out_size)
{
    (void)in_sizes; (void)n_in; (void)out_size;
    const float* q     = (const float*)d_in[0];
    const float* k     = (const float*)d_in[1];
    const float* v     = (const float*)d_in[2];
    const int*   vmask = (const int*)  d_in[3];
    const int*   qmask = (const int*)  d_in[4];
    const float* Wq = (const float*)d_in[6];
    const float* bq = (const float*)d_in[7];
    const float* Wk = (const float*)d_in[8];
    const float* bk = (const float*)d_in[9];
    const float* Wv = (const float*)d_in[10];
    const float* bv = (const float*)d_in[11];
    const float* Wo = (const float*)d_in[12];
    const float* bo = (const float*)d_in[13];
    float* out = (float*)d_out;

    // Capture-legal (no allocation, no enqueue); idempotent per call.
    cudaFuncSetAttribute(qkv_v5,
        cudaFuncAttributeMaxDynamicSharedMemorySize, GEMM_DSMEM);
    cudaFuncSetAttribute(out_v5,
        cudaFuncAttributeMaxDynamicSharedMemorySize, GEMM_DSMEM);
    cudaFuncSetAttribute(flash_v4,
        cudaFuncAttributeMaxDynamicSharedMemorySize, FLASH_DSMEM);

    conv_all<<<dim3(1024, 1, 7), 256>>>(q, k, v, Wq, Wk, Wv, Wo);
    qkv_v5<<<dim3(NN / BN, M / BM, 3), NTHR, GEMM_DSMEM>>>(bq, bk, bv);
    flash_v4<<<dim3(S / 128, B * H), 256, FLASH_DSMEM>>>(vmask);
    out_v5<<<dim3(NN / BN, M / BM), NTHR, GEMM_DSMEM>>>(bo, out, qmask);
}

// round 16
// speedup vs baseline: 1.1619x; 1.1619x over previous
#include <cuda_runtime.h>
#include <cuda_bf16.h>
#include <math.h>
#include <stdint.h>

// Problem constants
constexpr int B  = 4;
constexpr int S  = 1024;
constexpr int H  = 16;
constexpr int M  = B * S;          // 4096
constexpr int NN = H * 64;         // 1024
constexpr int KK = 1024;

// ===========================================================================
// Global scratch (device globals: allocation-free). bf16 hi/lo dataflow.
// ===========================================================================
__device__ __nv_bfloat16 g_xh[3][(size_t)M * KK];   // converted inputs q,k,v
__device__ __nv_bfloat16 g_xl[3][(size_t)M * KK];
__device__ __nv_bfloat16 g_wth[4][(size_t)NN * KK]; // transposed weights [n][k]
__device__ __nv_bfloat16 g_wtl[4][(size_t)NN * KK];
__device__ __nv_bfloat16 g_oh[3][(size_t)M * NN];   // qw,kw,vw (proj outputs)
__device__ __nv_bfloat16 g_ol[3][(size_t)M * NN];
__device__ __nv_bfloat16 g_ath[(size_t)M * NN];     // attention output
__device__ __nv_bfloat16 g_atl[(size_t)M * NN];

// ===========================================================================
// Helpers
// ===========================================================================
__device__ __forceinline__ uint32_t smem_u32(const void* p) {
    uint32_t a;
    asm("{ .reg .u64 t; cvta.to.shared.u64 t, %1; cvt.u32.u64 %0, t; }"
        : "=r"(a) : "l"(p));
    return a;
}
__device__ __forceinline__ uint64_t gaddr(const void* p) {
    uint64_t r;
    asm("cvta.to.global.u64 %0, %1;" : "=l"(r) : "l"(p));
    return r;
}
__device__ __forceinline__ uint32_t pk2(float a, float b) {
    __nv_bfloat162 t;
    t.x = __float2bfloat16(a);
    t.y = __float2bfloat16(b);
    return *(uint32_t*)&t;
}
__device__ __forceinline__ float bres(float x) {   // residual after bf16 hi
    __nv_bfloat16 h = __float2bfloat16(x);
    return x - __bfloat162float(h);
}

// 64B-row swizzle (GEMM tiles: 32 bf16 per row), chunk 0..3
__device__ __forceinline__ int sw_off(int row, int chunk) {
    return row * 64 + ((chunk ^ ((row >> 1) & 3) ^ ((row >> 3) & 3)) << 4);
}
// 128B-row swizzle (flash tiles: 64 bf16 per row), chunk 0..7
__device__ __forceinline__ int fsw(int row, int chunk) {
    return row * 128 + ((chunk ^ (row & 7)) << 4);
}

#define LDMX4(r, addr) \
    asm volatile("ldmatrix.sync.aligned.m8n8.x4.shared.b16 {%0,%1,%2,%3}, [%4];" \
        : "=r"((r)[0]), "=r"((r)[1]), "=r"((r)[2]), "=r"((r)[3]) : "r"(addr))
#define LDMX4T(r, addr) \
    asm volatile("ldmatrix.sync.aligned.m8n8.x4.trans.shared.b16 {%0,%1,%2,%3}, [%4];" \
        : "=r"((r)[0]), "=r"((r)[1]), "=r"((r)[2]), "=r"((r)[3]) : "r"(addr))
#define MMA_BF16(d, a, bb) \
    asm volatile("mma.sync.aligned.m16n8k16.row.col.f32.bf16.bf16.f32 " \
        "{%0,%1,%2,%3}, {%4,%5,%6,%7}, {%8,%9}, {%0,%1,%2,%3};" \
        : "+f"((d)[0]), "+f"((d)[1]), "+f"((d)[2]), "+f"((d)[3]) \
        : "r"((a)[0]), "r"((a)[1]), "r"((a)[2]), "r"((a)[3]), \
          "r"((bb)[0]), "r"((bb)[1]))
#define CP16(dst, src) \
    asm volatile("cp.async.cg.shared.global [%0], [%1], 16;" \
        :: "r"((uint32_t)(dst)), "l"((uint64_t)(src)))
#define CP_COMMIT() asm volatile("cp.async.commit_group;" ::: "memory")
#define CP_WAIT0()  asm volatile("cp.async.wait_group 0;" ::: "memory")
#define CP_WAIT1()  asm volatile("cp.async.wait_group 1;" ::: "memory")

// ===========================================================================
// Merged conversion kernel (z 0..2: inputs, z 3..6: transposed weights)
// ===========================================================================
__global__ void conv_all(const float* __restrict__ q,
                         const float* __restrict__ k,
                         const float* __restrict__ v,
                         const float* __restrict__ Wq,
                         const float* __restrict__ Wk,
                         const float* __restrict__ Wv,
                         const float* __restrict__ Wo)
{
    const int z = blockIdx.z;
    if (z < 3) {
        const float* src = (z == 0) ? q : (z == 1) ? k : v;
        uint2* dh = (uint2*)g_xh[z];
        uint2* dl = (uint2*)g_xl[z];
        const int n4 = M * KK / 4;
        for (int i = blockIdx.x * blockDim.x + threadIdx.x; i < n4;
             i += gridDim.x * blockDim.x) {
            float4 x = ((const float4*)src)[i];
            uint2 hi, lo;
            hi.x = pk2(x.x, x.y);             hi.y = pk2(x.z, x.w);
            lo.x = pk2(bres(x.x), bres(x.y)); lo.y = pk2(bres(x.z), bres(x.w));
            dh[i] = hi;
            dl[i] = lo;
        }
    } else {
        __shared__ float t[32][33];
        const int zw = z - 3;
        const float* W = (zw == 0) ? Wq : (zw == 1) ? Wk : (zw == 2) ? Wv : Wo;
        __nv_bfloat16* th = g_wth[zw];
        __nv_bfloat16* tl = g_wtl[zw];
        const int nb = (blockIdx.x & 31) * 32;
        const int kb = (blockIdx.x >> 5) * 32;
        const int tx = threadIdx.x & 31, ty = threadIdx.x >> 5;  // ty 0..7
#pragma unroll
        for (int j = 0; j < 4; ++j)
            t[ty + 8 * j][tx] = W[(size_t)(kb + ty + 8 * j) * NN + nb + tx];
        __syncthreads();
#pragma unroll
        for (int j = 0; j < 4; ++j) {
            const float val = t[tx][ty + 8 * j];
            const size_t o = (size_t)(nb + ty + 8 * j) * KK + kb + tx;
            __nv_bfloat16 h = __float2bfloat16(val);
            th[o] = h;
            tl[o] = __float2bfloat16(val - __bfloat162float(h));
        }
    }
}

// ===========================================================================
// cp.async bf16 split GEMM core v6: 128(M) x 128(N), BK=32, 256 threads,
// 8 warps in 4m x 2n grid, warp tile 32x64 (2 mt x 8 nt).
// Stage = 32KB (A hi/lo 8+8, B hi/lo 8+8). 3 stages = 96KB dynamic smem,
// prefetch depth 1, ONE __syncthreads per iter (write (t+1)%3 vs slowest
// reader (t-1)%3 — distinct mod 3). B frags loaded np-pairwise and consumed
// immediately (live B regs = 8). Arithmetic intensity: 128B smem per MMA
// (was 170) -> tensor-bound instead of LDS-bound.
// ===========================================================================
constexpr int BM = 128, BN = 128, BK = 32;
constexpr int STGB = 32768;
constexpr int AHI = 0, ALO = 8192, BHI = 16384, BLO = 24576;
constexpr int NT = KK / BK;
constexpr int GEMM_DSMEM  = 3 * STGB;            // 98304
constexpr int FLASH_DSMEM = 16384 + 3 * 32768;   // 114688

__device__ __forceinline__ void gemm_issue(uint64_t Ah, uint64_t Al,
                                           uint64_t Bh, uint64_t Bl,
                                           int k0, int tid, uint32_t stg)
{
    // 2048 x 16B chunks per stage; 8 per thread. p0,1: A hi; p2,3: A lo;
    // p4,5: B hi; p6,7: B lo. r = row 0..127, c = k-chunk 0..3.
#pragma unroll
    for (int p = 0; p < 8; ++p) {
        const int idx  = (tid + p * 256) & 511;      // within half
        const int r = idx >> 2, c = idx & 3;
        const uint64_t src =
            ((p < 2) ? Ah : (p < 4) ? Al : (p < 6) ? Bh : Bl)
            + (uint64_t)r * (KK * 2) + (uint64_t)(k0 + c * 8) * 2;
        const uint32_t soff =
            ((p < 2) ? AHI : (p < 4) ? ALO : (p < 6) ? BHI : BLO)
            + sw_off(r, c);
        CP16(stg + soff, src);
    }
}

__device__ __forceinline__ void gemm_core(uint64_t Ah, uint64_t Al,
                                          uint64_t Bh, uint64_t Bl,
                                          int m0, int n0, int lane,
                                          float acc[2][8][4])
{
    extern __shared__ __align__(128) char dynsm[];
    const uint32_t sbase = smem_u32(dynsm);
    const int tid = threadIdx.x;

#pragma unroll
    for (int mt = 0; mt < 2; ++mt)
#pragma unroll
        for (int nt = 0; nt < 8; ++nt)
#pragma unroll
            for (int i = 0; i < 4; ++i) acc[mt][nt][i] = 0.f;

    gemm_issue(Ah, Al, Bh, Bl, 0, tid, sbase);
    CP_COMMIT();

    for (int t = 0; t < NT; ++t) {
        if (t + 1 < NT) {
            gemm_issue(Ah, Al, Bh, Bl, (t + 1) * BK, tid,
                       sbase + ((t + 1) % 3) * STGB);
            CP_COMMIT();
            CP_WAIT1();
        } else {
            CP_WAIT0();
        }
        __syncthreads();

        const uint32_t sA = sbase + (t % 3) * STGB;
        const uint32_t sB = sA + BHI;
#pragma unroll
        for (int ks = 0; ks < 2; ++ks) {
            uint32_t ah[2][4], al[2][4];
#pragma unroll
            for (int mt = 0; mt < 2; ++mt) {
                const int row = m0 + mt * 16 + (lane & 15);
                const int ch  = ks * 2 + (lane >> 4);
                const uint32_t ad = sA + sw_off(row, ch);
                LDMX4(ah[mt], ad);
                LDMX4(al[mt], ad + ALO);
            }
#pragma unroll
            for (int np = 0; np < 4; ++np) {
                const int nr = n0 + np * 16 + ((lane >> 4) << 3) + (lane & 7);
                const int ch = ks * 2 + ((lane >> 3) & 1);
                const uint32_t ad = sB + sw_off(nr, ch);
                uint32_t th[4], tl[4];
                LDMX4(th, ad);
                LDMX4(tl, ad + (BLO - BHI));
                uint32_t b0h[2] = {th[0], th[1]}, b1h[2] = {th[2], th[3]};
                uint32_t b0l[2] = {tl[0], tl[1]}, b1l[2] = {tl[2], tl[3]};
#pragma unroll
                for (int mt = 0; mt < 2; ++mt) {
                    MMA_BF16(acc[mt][np * 2], ah[mt], b0h);
                    MMA_BF16(acc[mt][np * 2], ah[mt], b0l);
                    MMA_BF16(acc[mt][np * 2], al[mt], b0h);
                    MMA_BF16(acc[mt][np * 2 + 1], ah[mt], b1h);
                    MMA_BF16(acc[mt][np * 2 + 1], ah[mt], b1l);
                    MMA_BF16(acc[mt][np * 2 + 1], al[mt], b1h);
                }
            }
        }
        // single barrier per iter; 3-stage rotation covers write/read hazard
    }
}

// QKV projection: writes bf16 hi/lo outputs for flash
__global__ __launch_bounds__(256, 2)
void qkv_v6(const float* __restrict__ bq, const float* __restrict__ bk,
            const float* __restrict__ bv)
{
    const int z = blockIdx.z;
    const float* bias = (z == 0) ? bq : (z == 1) ? bk : bv;
    const int tid = threadIdx.x, lane = tid & 31, w = tid >> 5;
    const int m0 = (w >> 1) * 32, n0 = (w & 1) * 64;
    const int bm = blockIdx.y * BM, bn = blockIdx.x * BN;

    const uint64_t Ah = gaddr(g_xh[z])  + (uint64_t)bm * KK * 2;
    const uint64_t Al = gaddr(g_xl[z])  + (uint64_t)bm * KK * 2;
    const uint64_t Bh = gaddr(g_wth[z]) + (uint64_t)bn * KK * 2;
    const uint64_t Bl = gaddr(g_wtl[z]) + (uint64_t)bn * KK * 2;

    float acc[2][8][4];
    gemm_core(Ah, Al, Bh, Bl, m0, n0, lane, acc);

    __nv_bfloat16* Yh = g_oh[z];
    __nv_bfloat16* Yl = g_ol[z];
#pragma unroll
    for (int nt = 0; nt < 8; ++nt) {
        const int gc = bn + n0 + nt * 8 + (lane & 3) * 2;
        const float b0 = bias[gc], b1 = bias[gc + 1];
#pragma unroll
        for (int mt = 0; mt < 2; ++mt) {
            const int gr = bm + m0 + mt * 16 + (lane >> 2);
            const float y0 = acc[mt][nt][0] + b0;
            const float y1 = acc[mt][nt][1] + b1;
            const float y2 = acc[mt][nt][2] + b0;
            const float y3 = acc[mt][nt][3] + b1;
            *(uint32_t*)&Yh[(size_t)gr * NN + gc]       = pk2(y0, y1);
            *(uint32_t*)&Yl[(size_t)gr * NN + gc]       = pk2(bres(y0), bres(y1));
            *(uint32_t*)&Yh[(size_t)(gr + 8) * NN + gc] = pk2(y2, y3);
            *(uint32_t*)&Yl[(size_t)(gr + 8) * NN + gc] = pk2(bres(y2), bres(y3));
        }
    }
}

// Output projection: A = attention output (bf16 hi/lo), fp32 out, q_mask
__global__ __launch_bounds__(256, 2)
void out_v6(const float* __restrict__ bo, float* __restrict__ out,
            const int* __restrict__ qmask)
{
    const int tid = threadIdx.x, lane = tid & 31, w = tid >> 5;
    const int m0 = (w >> 1) * 32, n0 = (w & 1) * 64;
    const int bm = blockIdx.y * BM, bn = blockIdx.x * BN;

    const uint64_t Ah = gaddr(g_ath)    + (uint64_t)bm * KK * 2;
    const uint64_t Al = gaddr(g_atl)    + (uint64_t)bm * KK * 2;
    const uint64_t Bh = gaddr(g_wth[3]) + (uint64_t)bn * KK * 2;
    const uint64_t Bl = gaddr(g_wtl[3]) + (uint64_t)bn * KK * 2;

    float acc[2][8][4];
    gemm_core(Ah, Al, Bh, Bl, m0, n0, lane, acc);

#pragma unroll
    for (int nt = 0; nt < 8; ++nt) {
        const int gc = bn + n0 + nt * 8 + (lane & 3) * 2;
        const float b0 = bo[gc], b1 = bo[gc + 1];
#pragma unroll
        for (int mt = 0; mt < 2; ++mt) {
            const int gr = bm + m0 + mt * 16 + (lane >> 2);
            const float s0 = (float)qmask[gr];
            const float s1 = (float)qmask[gr + 8];
            float2 v0, v1;
            v0.x = (acc[mt][nt][0] + b0) * s0;
            v0.y = (acc[mt][nt][1] + b1) * s0;
            v1.x = (acc[mt][nt][2] + b0) * s1;
            v1.y = (acc[mt][nt][3] + b1) * s1;
            *(float2*)(out + (size_t)gr * NN + gc)       = v0;
            *(float2*)(out + (size_t)(gr + 8) * NN + gc) = v1;
        }
    }
}

// ===========================================================================
// Flash attention v4 (R13 design, unchanged numerics): 128 q-rows/CTA,
// 8 warps, 3 KV stages, cp.async depth 1, one __syncthreads per tile.
// Only change: q-tile index REVERSED so heavy (large-diagonal) CTAs launch
// first — light early-exit CTAs fill the second-wave tail.
// ===========================================================================
constexpr int FQB = 0, FSTG0 = 16384, FSTGB = 32768;
constexpr int FKL_O = 8192, FVH_O = 16384, FVL_O = 24576;  // within stage

__device__ __forceinline__ void flash_issue(uint64_t Kh, uint64_t Kl,
                                            uint64_t Vh, uint64_t Vl,
                                            int b, int t, int hc, int tid,
                                            uint32_t stg)
{
#pragma unroll
    for (int i = 0; i < 2; ++i) {
        const int id = tid + i * 256;
        const int r = id >> 3, c = id & 7;
        const uint64_t off = ((uint64_t)(b * S + t * 64 + r) * NN + hc + c * 8) * 2;
        const int sw = fsw(r, c);
        CP16(stg + sw,         Kh + off);
        CP16(stg + FKL_O + sw, Kl + off);
        CP16(stg + FVH_O + sw, Vh + off);
        CP16(stg + FVL_O + sw, Vl + off);
    }
}

__global__ __launch_bounds__(256, 2)
void flash_v4(const int* __restrict__ v_mask)
{
    extern __shared__ __align__(128) char dynsm[];
    const uint32_t sb = smem_u32(dynsm);
    const int tid  = threadIdx.x;
    const int lane = tid & 31;
    const int w    = tid >> 5;         // 0..7
    const int m0   = w * 16;           // 0..112
    const int bh   = blockIdx.y;
    const int b    = bh >> 4;
    const int h    = bh & 15;
    const int bxr  = (int)gridDim.x - 1 - (int)blockIdx.x;  // heavy first
    const int q0   = bxr * 128;
    const int hc   = h * 64;

    const uint64_t Qh = gaddr(g_oh[0]);
    const uint64_t Ql = gaddr(g_ol[0]);
    const uint64_t Kh = gaddr(g_oh[1]);
    const uint64_t Kl = gaddr(g_ol[1]);
    const uint64_t Vh = gaddr(g_oh[2]);
    const uint64_t Vl = gaddr(g_ol[2]);

    // ---- Q phase 1: hi into QB, read frags ----
    uint32_t qh[4][4], ql[4][4];
    {
#pragma unroll
        for (int i = 0; i < 4; ++i) {
            const int id = tid + i * 256;
            const int r = id >> 3, c = id & 7;
            CP16(sb + FQB + fsw(r, c),
                 Qh + ((uint64_t)(b * S + q0 + r) * NN + hc + c * 8) * 2);
        }
        CP_COMMIT(); CP_WAIT0();
    }
    __syncthreads();
#pragma unroll
    for (int ks = 0; ks < 4; ++ks) {
        const int row = m0 + (lane & 15);
        const int ch  = ks * 2 + (lane >> 4);
        LDMX4(qh[ks], sb + FQB + fsw(row, ch));
    }
    __syncthreads();
    // ---- Q phase 2: lo into QB (reuse), read frags ----
    {
#pragma unroll
        for (int i = 0; i < 4; ++i) {
            const int id = tid + i * 256;
            const int r = id >> 3, c = id & 7;
            CP16(sb + FQB + fsw(r, c),
                 Ql + ((uint64_t)(b * S + q0 + r) * NN + hc + c * 8) * 2);
        }
        CP_COMMIT(); CP_WAIT0();
    }
    __syncthreads();
#pragma unroll
    for (int ks = 0; ks < 4; ++ks) {
        const int row = m0 + (lane & 15);
        const int ch  = ks * 2 + (lane >> 4);
        LDMX4(ql[ks], sb + FQB + fsw(row, ch));
    }

    const float NEGINF = __int_as_float(0xff800000);
    float m_[2] = {NEGINF, NEGINF};
    float l_[2] = {0.f, 0.f};
    float o[8][4];
#pragma unroll
    for (int nt = 0; nt < 8; ++nt)
#pragma unroll
        for (int i = 0; i < 4; ++i) o[nt][i] = 0.f;

    const int diag2 = 2 * bxr + 1;   // last causal-needed tile

    // prefetch KV tile 0 -> stage 0
    flash_issue(Kh, Kl, Vh, Vl, b, 0, hc, tid, sb + FSTG0);
    CP_COMMIT();

    int s_cur = 0, s_nxt = 1;
    for (int t = 0; t < 16; ++t) {
        if (t + 1 < 16) {
            flash_issue(Kh, Kl, Vh, Vl, b, t + 1, hc, tid,
                        sb + FSTG0 + s_nxt * FSTGB);
            CP_COMMIT();
            CP_WAIT1();
        } else {
            CP_WAIT0();
        }
        __syncthreads();

        const uint32_t sK = sb + FSTG0 + s_cur * FSTGB;
        const uint32_t sV = sK + FVH_O;

        // ---- S = Q K^T (split-bf16, 3 passes) ----
        float sc[8][4];
#pragma unroll
        for (int nt = 0; nt < 8; ++nt)
#pragma unroll
            for (int i = 0; i < 4; ++i) sc[nt][i] = 0.f;
#pragma unroll
        for (int ks = 0; ks < 4; ++ks) {
            uint32_t kbh[8][2], kbl[8][2];
#pragma unroll
            for (int np = 0; np < 4; ++np) {
                const int nr = np * 16 + ((lane >> 4) << 3) + (lane & 7);
                const int ch = ks * 2 + ((lane >> 3) & 1);
                const uint32_t ad = sK + fsw(nr, ch);
                uint32_t th[4], tl[4];
                LDMX4(th, ad);
                LDMX4(tl, ad + FKL_O);
                kbh[np * 2][0] = th[0]; kbh[np * 2][1] = th[1];
                kbh[np * 2 + 1][0] = th[2]; kbh[np * 2 + 1][1] = th[3];
                kbl[np * 2][0] = tl[0]; kbl[np * 2][1] = tl[1];
                kbl[np * 2 + 1][0] = tl[2]; kbl[np * 2 + 1][1] = tl[3];
            }
#pragma unroll
            for (int nt = 0; nt < 8; ++nt) {
                MMA_BF16(sc[nt], qh[ks], kbh[nt]);
                MMA_BF16(sc[nt], qh[ks], kbl[nt]);
                MMA_BF16(sc[nt], ql[ks], kbh[nt]);
            }
        }

        // ---- mask + online softmax (v_mask from global/L1) ----
        const int r0g = q0 + m0 + (lane >> 2);
        const int r1g = r0g + 8;
        const int vmb = b * S + t * 64;
        float tmax0 = NEGINF, tmax1 = NEGINF;
#pragma unroll
        for (int nt = 0; nt < 8; ++nt) {
            const int c0  = nt * 8 + (lane & 3) * 2;
            const int cg0 = t * 64 + c0;
            const float p0 = (1.0f - (float)__ldg(&v_mask[vmb + c0]))     * 1e12f;
            const float p1 = (1.0f - (float)__ldg(&v_mask[vmb + c0 + 1])) * 1e12f;
            float s0 = sc[nt][0] * 0.125f - p0; if (cg0     > r0g) s0 -= 1e12f;
            float s1 = sc[nt][1] * 0.125f - p1; if (cg0 + 1 > r0g) s1 -= 1e12f;
            float s2 = sc[nt][2] * 0.125f - p0; if (cg0     > r1g) s2 -= 1e12f;
            float s3 = sc[nt][3] * 0.125f - p1; if (cg0 + 1 > r1g) s3 -= 1e12f;
            sc[nt][0] = s0; sc[nt][1] = s1; sc[nt][2] = s2; sc[nt][3] = s3;
            tmax0 = fmaxf(tmax0, fmaxf(s0, s1));
            tmax1 = fmaxf(tmax1, fmaxf(s2, s3));
        }
        tmax0 = fmaxf(tmax0, __shfl_xor_sync(0xffffffffu, tmax0, 1));
        tmax0 = fmaxf(tmax0, __shfl_xor_sync(0xffffffffu, tmax0, 2));
        tmax1 = fmaxf(tmax1, __shfl_xor_sync(0xffffffffu, tmax1, 1));
        tmax1 = fmaxf(tmax1, __shfl_xor_sync(0xffffffffu, tmax1, 2));
        const float mn0 = fmaxf(m_[0], tmax0);
        const float mn1 = fmaxf(m_[1], tmax1);
        const float al0 = __expf(m_[0] - mn0);
        const float al1 = __expf(m_[1] - mn1);
        float rs0 = 0.f, rs1 = 0.f;
#pragma unroll
        for (int nt = 0; nt < 8; ++nt) {
            sc[nt][0] = __expf(sc[nt][0] - mn0); rs0 += sc[nt][0];
            sc[nt][1] = __expf(sc[nt][1] - mn0); rs0 += sc[nt][1];
            sc[nt][2] = __expf(sc[nt][2] - mn1); rs1 += sc[nt][2];
            sc[nt][3] = __expf(sc[nt][3] - mn1); rs1 += sc[nt][3];
        }
        rs0 += __shfl_xor_sync(0xffffffffu, rs0, 1);
        rs0 += __shfl_xor_sync(0xffffffffu, rs0, 2);
        rs1 += __shfl_xor_sync(0xffffffffu, rs1, 1);
        rs1 += __shfl_xor_sync(0xffffffffu, rs1, 2);
        l_[0] = l_[0] * al0 + rs0;
        l_[1] = l_[1] * al1 + rs1;
        m_[0] = mn0;
        m_[1] = mn1;
#pragma unroll
        for (int nt = 0; nt < 8; ++nt) {
            o[nt][0] *= al0; o[nt][1] *= al0;
            o[nt][2] *= al1; o[nt][3] *= al1;
        }

        // ---- O += P V (P repacked in registers; V via ldmatrix.trans) ----
#pragma unroll
        for (int kt = 0; kt < 4; ++kt) {
            uint32_t pah[4], pal[4];
            pah[0] = pk2(sc[2 * kt][0],     sc[2 * kt][1]);
            pah[1] = pk2(sc[2 * kt][2],     sc[2 * kt][3]);
            pah[2] = pk2(sc[2 * kt + 1][0], sc[2 * kt + 1][1]);
            pah[3] = pk2(sc[2 * kt + 1][2], sc[2 * kt + 1][3]);
            pal[0] = pk2(bres(sc[2 * kt][0]),     bres(sc[2 * kt][1]));
            pal[1] = pk2(bres(sc[2 * kt][2]),     bres(sc[2 * kt][3]));
            pal[2] = pk2(bres(sc[2 * kt + 1][0]), bres(sc[2 * kt + 1][1]));
            pal[3] = pk2(bres(sc[2 * kt + 1][2]), bres(sc[2 * kt + 1][3]));
#pragma unroll
            for (int np = 0; np < 4; ++np) {
                const int key = kt * 16 + (lane & 7) + ((lane >> 3) & 1) * 8;
                const int ch  = np * 2 + (lane >> 4);
                const uint32_t ad = sV + fsw(key, ch);
                uint32_t vh4[4], vl4[4];
                LDMX4T(vh4, ad);
                LDMX4T(vl4, ad + (FVL_O - FVH_O));
                uint32_t vb0h[2] = {vh4[0], vh4[1]}, vb1h[2] = {vh4[2], vh4[3]};
                uint32_t vb0l[2] = {vl4[0], vl4[1]}, vb1l[2] = {vl4[2], vl4[3]};
                MMA_BF16(o[np * 2],     pah, vb0h);
                MMA_BF16(o[np * 2],     pah, vb0l);
                MMA_BF16(o[np * 2],     pal, vb0h);
                MMA_BF16(o[np * 2 + 1], pah, vb1h);
                MMA_BF16(o[np * 2 + 1], pah, vb1l);
                MMA_BF16(o[np * 2 + 1], pal, vb1h);
            }
        }

        // Past diagonal: continue only while some row is still fully masked
        if (t >= diag2) {
            int pred = (mn0 <= -1e11f) | (mn1 <= -1e11f);
            if (!__syncthreads_or(pred)) break;
        }
        s_cur = (s_cur == 2) ? 0 : s_cur + 1;
        s_nxt = (s_nxt == 2) ? 0 : s_nxt + 1;
    }

    // ---- normalize + store as bf16 hi/lo for the output projection ----
    const float inv0 = 1.0f / l_[0];
    const float inv1 = 1.0f / l_[1];
    const int gr0 = b * S + q0 + m0 + (lane >> 2);
#pragma unroll
    for (int nt = 0; nt < 8; ++nt) {
        const int col = hc + nt * 8 + (lane & 3) * 2;
        const float a0 = o[nt][0] * inv0, a1 = o[nt][1] * inv0;
        const float a2 = o[nt][2] * inv1, a3 = o[nt][3] * inv1;
        *(uint32_t*)&g_ath[(size_t)gr0 * NN + col]       = pk2(a0, a1);
        *(uint32_t*)&g_atl[(size_t)gr0 * NN + col]       = pk2(bres(a0), bres(a1));
        *(uint32_t*)&g_ath[(size_t)(gr0 + 8) * NN + col] = pk2(a2, a3);
        *(uint32_t*)&g_atl[(size_t)(gr0 + 8) * NN + col] = pk2(bres(a2), bres(a3));
    }
}

// ---------------------------------------------------------------------------
extern "C" void kernel_launch(void* const* d_in, const int* in_sizes, int n_in,
                              void* d_out, int out_size)
{
    (void)in_sizes; (void)n_in; (void)out_size;
    const float* q     = (const float*)d_in[0];
    const float* k     = (const float*)d_in[1];
    const float* v     = (const float*)d_in[2];
    const int*   vmask = (const int*)  d_in[3];
    const int*   qmask = (const int*)  d_in[4];
    const float* Wq = (const float*)d_in[6];
    const float* bq = (const float*)d_in[7];
    const float* Wk = (const float*)d_in[8];
    const float* bk = (const float*)d_in[9];
    const float* Wv = (const float*)d_in[10];
    const float* bv = (const float*)d_in[11];
    const float* Wo = (const float*)d_in[12];
    const float* bo = (const float*)d_in[13];
    float* out = (float*)d_out;

    // Capture-legal (no allocation, no enqueue); idempotent per call.
    cudaFuncSetAttribute(qkv_v6,
        cudaFuncAttributeMaxDynamicSharedMemorySize, GEMM_DSMEM);
    cudaFuncSetAttribute(out_v6,
        cudaFuncAttributeMaxDynamicSharedMemorySize, GEMM_DSMEM);
    cudaFuncSetAttribute(flash_v4,
        cudaFuncAttributeMaxDynamicSharedMemorySize, FLASH_DSMEM);

    conv_all<<<dim3(1024, 1, 7), 256>>>(q, k, v, Wq, Wk, Wv, Wo);
    qkv_v6<<<dim3(NN / BN, M / BM, 3), 256, GEMM_DSMEM>>>(bq, bk, bv);
    flash_v4<<<dim3(S / 128, B * H), 256, FLASH_DSMEM>>>(vmask);
    out_v6<<<dim3(NN / BN, M / BM), 256, GEMM_DSMEM>>>(bo, out, qmask);
}